// round 5
// baseline (speedup 1.0000x reference)
#include <cuda_runtime.h>
#include <cuda_bf16.h>
#include <cstdint>

// ---------------------------------------------------------------------------
// fusionEncodeBlock: B=2, S=1024, D=256, H=4, C=64, FF=2048, WIN=10, NITER=2
// bf16x2 split GEMMs (3-product, fp32 accumulate) on mma.sync tensor cores.
// LN / softmax-attention core / epilogues in fp32. State in d_out.
// ---------------------------------------------------------------------------

#define Bb   2
#define Ss   1024
#define Dd   256
#define Hh   4
#define Cc   64
#define FFD  2048
#define RR   (Bb * Ss)          // 2048 rows
#define RD   (RR * Dd)          // 524288
#define WIN  10

typedef __nv_bfloat16 bf16;

// ---------------- scratch (allocation-free; 16B-aligned for uint4 access) ---
__device__ __align__(16) float g_Q[RD];
__device__ __align__(16) float g_K[RD];
__device__ __align__(16) float g_V[RD];
__device__ __align__(16) float g_G[RD];

__device__ __align__(16) bf16 g_t1h[RD], g_t1l[RD];
__device__ __align__(16) bf16 g_t2h[RD], g_t2l[RD];
__device__ __align__(16) bf16 g_t3h[RD], g_t3l[RD];
__device__ __align__(16) bf16 g_atth[RD], g_attl[RD];
__device__ __align__(16) bf16 g_hidh[RR * FFD], g_hidl[RR * FFD];

// split + transposed weights: stored [mat][N][K]
__device__ __align__(16) bf16 g_wqh[7 * Dd * Dd],  g_wql[7 * Dd * Dd];
__device__ __align__(16) bf16 g_wkh[7 * Dd * Dd],  g_wkl[7 * Dd * Dd];
__device__ __align__(16) bf16 g_wvh[7 * Dd * Dd],  g_wvl[7 * Dd * Dd];
__device__ __align__(16) bf16 g_wgh[7 * Dd * Dd],  g_wgl[7 * Dd * Dd];
__device__ __align__(16) bf16 g_woh[7 * Dd * Dd],  g_wol[7 * Dd * Dd];
__device__ __align__(16) bf16 g_w1h[6 * Dd * FFD], g_w1l[6 * Dd * FFD];
__device__ __align__(16) bf16 g_w2h[6 * FFD * Dd], g_w2l[6 * FFD * Dd];

// ---------------------------------------------------------------------------
__global__ void init_copy_kernel(const float* __restrict__ a,
                                 const float* __restrict__ b,
                                 const float* __restrict__ c,
                                 float* __restrict__ out) {
    int i = blockIdx.x * blockDim.x + threadIdx.x;
    out[i]          = a[i];
    out[i + RD]     = b[i];
    out[i + 2 * RD] = c[i];
}

// ---------------------------------------------------------------------------
// Split + transpose weights: src [mat][K][N] fp32 -> hi/lo [mat][N][K] bf16.
// i enumerates outputs (k fastest) -> coalesced writes.
__global__ void split_w_kernel(const float* __restrict__ src,
                               bf16* __restrict__ hi, bf16* __restrict__ lo,
                               int K, int N, int total) {
    int i = blockIdx.x * blockDim.x + threadIdx.x;
    if (i >= total) return;
    int kn  = K * N;
    int mat = i / kn;
    int r   = i - mat * kn;
    int k   = r % K;
    int n   = r / K;
    float v = src[(size_t)mat * kn + (size_t)k * N + n];
    bf16 h = __float2bfloat16(v);
    hi[i] = h;
    lo[i] = __float2bfloat16(v - __bfloat162float(h));
}

// ---------------------------------------------------------------------------
// LayerNorm over last dim (256), emits bf16 hi/lo split. One block per row.
__global__ void __launch_bounds__(Dd) ln_kernel(const float* __restrict__ x,
                                                const float* __restrict__ g,
                                                const float* __restrict__ b,
                                                bf16* __restrict__ oh,
                                                bf16* __restrict__ ol) {
    int row = blockIdx.x;
    int tid = threadIdx.x;
    float v = x[(size_t)row * Dd + tid];

    float s = v;
    #pragma unroll
    for (int o = 16; o; o >>= 1) s += __shfl_xor_sync(0xffffffffu, s, o);

    __shared__ float ws[8];
    __shared__ float ws2[8];
    int w = tid >> 5, l = tid & 31;
    if (l == 0) ws[w] = s;
    __syncthreads();
    float mean = (ws[0] + ws[1] + ws[2] + ws[3] +
                  ws[4] + ws[5] + ws[6] + ws[7]) * (1.0f / Dd);

    float d = v - mean;
    float sq = d * d;
    #pragma unroll
    for (int o = 16; o; o >>= 1) sq += __shfl_xor_sync(0xffffffffu, sq, o);
    if (l == 0) ws2[w] = sq;
    __syncthreads();
    float var = (ws2[0] + ws2[1] + ws2[2] + ws2[3] +
                 ws2[4] + ws2[5] + ws2[6] + ws2[7]) * (1.0f / Dd);

    float y = d * rsqrtf(var + 1e-5f) * g[tid] + b[tid];
    bf16 h = __float2bfloat16(y);
    oh[(size_t)row * Dd + tid] = h;
    ol[(size_t)row * Dd + tid] = __float2bfloat16(y - __bfloat162float(h));
}

// ---------------------------------------------------------------------------
__device__ __forceinline__ void mma_bf16(float* c,
                                         uint32_t a0, uint32_t a1,
                                         uint32_t a2, uint32_t a3,
                                         uint32_t b0, uint32_t b1) {
    asm volatile(
        "mma.sync.aligned.m16n8k16.row.col.f32.bf16.bf16.f32 "
        "{%0,%1,%2,%3}, {%4,%5,%6,%7}, {%8,%9}, {%0,%1,%2,%3};"
        : "+f"(c[0]), "+f"(c[1]), "+f"(c[2]), "+f"(c[3])
        : "r"(a0), "r"(a1), "r"(a2), "r"(a3), "r"(b0), "r"(b1));
}

// ---------------------------------------------------------------------------
// Split-bf16 GEMM body. C[M,N] = A[M,K] @ W[K,N] where operands come pre-split:
//   A as hi/lo bf16 row-major [M][K]; W as hi/lo bf16 TRANSPOSED [N][K].
// acc = Ah*Wh + Ah*Wl + Al*Wh (fp32 accumulate) ~ fp32-accurate.
// Tile: BM=64 x BN=NT*8, 128 threads (4 warps; warp w owns rows w*16..w*16+15).
// k-panel 16, smem double-buffered via register prefetch, 1 sync per panel.
// EPI: 0: C=AB   1: C=sigmoid(AB+bias)   2: C+=AB+bias   3: hi/lo=split(relu(AB+bias))
template <int NT, int EPI>
__device__ __forceinline__ void mma_gemm_body(
    const bf16* __restrict__ Ah, const bf16* __restrict__ Al,
    const bf16* __restrict__ Wh, const bf16* __restrict__ Wl,
    const float* __restrict__ bias,
    float* __restrict__ C, bf16* __restrict__ Chi, bf16* __restrict__ Clo,
    int N, int K) {

    constexpr int BN   = NT * 8;
    constexpr int NSEG = (256 + 4 * BN) / 128;   // uint4 segments per thread

    __shared__ bf16 Ash[2][64][24], Asl[2][64][24];
    __shared__ bf16 Wsh[2][BN][24], Wsl[2][BN][24];

    int tid  = threadIdx.x;
    int warp = tid >> 5, lane = tid & 31;
    int bm = blockIdx.y * 64, bn = blockIdx.x * BN;

    // ---- segment decode (A: 256 segs of 8 bf16; W: 4*BN segs) ----
    const bf16* sbase[NSEG];
    bf16*       dbase[NSEG];
    int         dstr[NSEG];
    #pragma unroll
    for (int i = 0; i < NSEG; i++) {
        int s = tid + i * 128;
        if (s < 256) {
            int hilo = s >> 7, r = (s >> 1) & 63, koff = (s & 1) * 8;
            sbase[i] = (hilo ? Al : Ah) + (size_t)(bm + r) * K + koff;
            dbase[i] = (hilo ? &Asl[0][0][0] : &Ash[0][0][0]) + r * 24 + koff;
            dstr[i]  = 64 * 24;
        } else {
            int t = s - 256;
            int hilo = t / (2 * BN), n = (t >> 1) & (BN - 1), koff = (t & 1) * 8;
            sbase[i] = (hilo ? Wl : Wh) + (size_t)(bn + n) * K + koff;
            dbase[i] = (hilo ? &Wsl[0][0][0] : &Wsh[0][0][0]) + n * 24 + koff;
            dstr[i]  = BN * 24;
        }
    }

    uint4 pref[NSEG];
    #pragma unroll
    for (int i = 0; i < NSEG; i++) pref[i] = *(const uint4*)(sbase[i]);
    #pragma unroll
    for (int i = 0; i < NSEG; i++) *(uint4*)(dbase[i]) = pref[i];
    __syncthreads();

    int g  = lane >> 2;
    int q2 = (lane & 3) << 1;
    int r0 = warp * 16 + g;

    float acc[NT][4];
    #pragma unroll
    for (int nt = 0; nt < NT; nt++)
        #pragma unroll
        for (int j = 0; j < 4; j++) acc[nt][j] = 0.0f;

    int npanel = K >> 4;
    for (int p = 0; p < npanel; p++) {
        int buf = p & 1;
        bool more = (p + 1) < npanel;
        if (more) {
            int k0 = (p + 1) << 4;
            #pragma unroll
            for (int i = 0; i < NSEG; i++)
                pref[i] = *(const uint4*)(sbase[i] + k0);
        }

        // A fragments (m16n8k16 layout)
        uint32_t ah0 = *(const uint32_t*)&Ash[buf][r0][q2];
        uint32_t ah1 = *(const uint32_t*)&Ash[buf][r0 + 8][q2];
        uint32_t ah2 = *(const uint32_t*)&Ash[buf][r0][q2 + 8];
        uint32_t ah3 = *(const uint32_t*)&Ash[buf][r0 + 8][q2 + 8];
        uint32_t al0 = *(const uint32_t*)&Asl[buf][r0][q2];
        uint32_t al1 = *(const uint32_t*)&Asl[buf][r0 + 8][q2];
        uint32_t al2 = *(const uint32_t*)&Asl[buf][r0][q2 + 8];
        uint32_t al3 = *(const uint32_t*)&Asl[buf][r0 + 8][q2 + 8];

        #pragma unroll
        for (int nt = 0; nt < NT; nt++) {
            int nn = nt * 8 + g;
            uint32_t bh0 = *(const uint32_t*)&Wsh[buf][nn][q2];
            uint32_t bh1 = *(const uint32_t*)&Wsh[buf][nn][q2 + 8];
            uint32_t bl0 = *(const uint32_t*)&Wsl[buf][nn][q2];
            uint32_t bl1 = *(const uint32_t*)&Wsl[buf][nn][q2 + 8];
            mma_bf16(acc[nt], ah0, ah1, ah2, ah3, bh0, bh1);   // hi*hi
            mma_bf16(acc[nt], ah0, ah1, ah2, ah3, bl0, bl1);   // hi*lo
            mma_bf16(acc[nt], al0, al1, al2, al3, bh0, bh1);   // lo*hi
        }

        if (more) {
            int nb = buf ^ 1;
            #pragma unroll
            for (int i = 0; i < NSEG; i++)
                *(uint4*)(dbase[i] + nb * dstr[i]) = pref[i];
            __syncthreads();
        }
    }

    // ---- epilogue: c0,c1 -> (r0, col..col+1); c2,c3 -> (r0+8, ...) ----
    int row0 = bm + r0;
    #pragma unroll
    for (int nt = 0; nt < NT; nt++) {
        int col = bn + nt * 8 + q2;
        #pragma unroll
        for (int half = 0; half < 2; half++) {
            int row = row0 + half * 8;
            float v0 = acc[nt][half * 2 + 0];
            float v1 = acc[nt][half * 2 + 1];
            size_t o = (size_t)row * N + col;
            if (EPI == 0) {
                *(float2*)&C[o] = make_float2(v0, v1);
            } else if (EPI == 1) {
                v0 += bias[col];     v1 += bias[col + 1];
                v0 = 1.0f / (1.0f + __expf(-v0));
                v1 = 1.0f / (1.0f + __expf(-v1));
                *(float2*)&C[o] = make_float2(v0, v1);
            } else if (EPI == 2) {
                float2 old = *(float2*)&C[o];
                *(float2*)&C[o] = make_float2(old.x + v0 + bias[col],
                                              old.y + v1 + bias[col + 1]);
            } else {
                v0 = fmaxf(v0 + bias[col],     0.0f);
                v1 = fmaxf(v1 + bias[col + 1], 0.0f);
                bf16 h0 = __float2bfloat16(v0);
                bf16 h1 = __float2bfloat16(v1);
                __nv_bfloat162 hv; hv.x = h0; hv.y = h1;
                __nv_bfloat162 lv;
                lv.x = __float2bfloat16(v0 - __bfloat162float(h0));
                lv.y = __float2bfloat16(v1 - __bfloat162float(h1));
                *(__nv_bfloat162*)&Chi[o] = hv;
                *(__nv_bfloat162*)&Clo[o] = lv;
            }
        }
    }
}

template <int NT, int EPI>
__global__ void __launch_bounds__(128) mma_gemm_kernel(
    const bf16* __restrict__ Ah, const bf16* __restrict__ Al,
    const bf16* __restrict__ Wh, const bf16* __restrict__ Wl,
    const float* __restrict__ bias,
    float* __restrict__ C, bf16* __restrict__ Chi, bf16* __restrict__ Clo,
    int N, int K) {
    mma_gemm_body<NT, EPI>(Ah, Al, Wh, Wl, bias, C, Chi, Clo, N, K);
}

// Fused Q/K/V/G projection: blockIdx.z selects operand set (NT=4, BN=32).
__global__ void __launch_bounds__(128) mma_qkvg_kernel(
    const bf16* __restrict__ qh, const bf16* __restrict__ ql,
    const bf16* __restrict__ kvh, const bf16* __restrict__ kvl,
    const bf16* __restrict__ Wqh, const bf16* __restrict__ Wql,
    const bf16* __restrict__ Wkh, const bf16* __restrict__ Wkl,
    const bf16* __restrict__ Wvh, const bf16* __restrict__ Wvl,
    const bf16* __restrict__ Wgh, const bf16* __restrict__ Wgl,
    const float* __restrict__ Gb,
    float* __restrict__ Qo, float* __restrict__ Ko,
    float* __restrict__ Vo, float* __restrict__ Go) {

    int z = blockIdx.z;
    const bf16* Ah = (z == 0) ? qh : kvh;
    const bf16* Al = (z == 0) ? ql : kvl;
    const bf16* Wh = (z == 0) ? Wqh : (z == 1) ? Wkh : (z == 2) ? Wvh : Wgh;
    const bf16* Wl = (z == 0) ? Wql : (z == 1) ? Wkl : (z == 2) ? Wvl : Wgl;
    float* C       = (z == 0) ? Qo : (z == 1) ? Ko : (z == 2) ? Vo : Go;

    if (z == 3) mma_gemm_body<4, 1>(Ah, Al, Wh, Wl, Gb, C, nullptr, nullptr, Dd, Dd);
    else        mma_gemm_body<4, 0>(Ah, Al, Wh, Wl, nullptr, C, nullptr, nullptr, Dd, Dd);
}

// ---------------------------------------------------------------------------
// Local-window gated attention core (fp32). One warp per (n, h, s).
// Emits att as bf16 hi/lo split for the projection GEMM.
__global__ void __launch_bounds__(128) attn_core_kernel(
    const float* __restrict__ Q, const float* __restrict__ Kp,
    const float* __restrict__ V, const float* __restrict__ G,
    const unsigned char* __restrict__ mask,
    bf16* __restrict__ outh, bf16* __restrict__ outl) {

    int wid  = blockIdx.x * 4 + (threadIdx.x >> 5);
    int lane = threadIdx.x & 31;
    int s = wid & (Ss - 1);
    int h = (wid >> 10) & (Hh - 1);
    int n = wid >> 12;

    const float* Qr = Q + (size_t)(n * Ss + s) * Dd + h * Cc;
    float q0 = Qr[lane], q1 = Qr[lane + 32];

    float sc[2 * WIN + 1];
    float m = -1e30f;
    #pragma unroll
    for (int i = 0; i < 2 * WIN + 1; i++) {
        int t  = s - WIN + i;
        int tc = min(max(t, 0), Ss - 1);
        const float* Kr = Kp + (size_t)(n * Ss + tc) * Dd + h * Cc;
        float p = q0 * Kr[lane] + q1 * Kr[lane + 32];
        #pragma unroll
        for (int o = 16; o; o >>= 1) p += __shfl_xor_sync(0xffffffffu, p, o);
        p *= 0.125f;                                   // 1/sqrt(64)
        if (t != tc || mask[n * Ss + tc]) p = -1e30f;  // window edge / seq mask
        sc[i] = p;
        m = fmaxf(m, p);
    }

    float den = 0.0f;
    #pragma unroll
    for (int i = 0; i < 2 * WIN + 1; i++) {
        sc[i] = __expf(sc[i] - m);
        den += sc[i];
    }
    float inv = 1.0f / den;

    float a0 = 0.0f, a1 = 0.0f;
    #pragma unroll
    for (int i = 0; i < 2 * WIN + 1; i++) {
        int t  = s - WIN + i;
        int tc = min(max(t, 0), Ss - 1);
        const float* Vr = V + (size_t)(n * Ss + tc) * Dd + h * Cc;
        float w = sc[i] * inv;
        a0 += w * Vr[lane];
        a1 += w * Vr[lane + 32];
    }

    size_t o = (size_t)(n * Ss + s) * Dd + h * Cc;
    float v0 = a0 * G[o + lane];
    float v1 = a1 * G[o + lane + 32];
    bf16 h0 = __float2bfloat16(v0);
    bf16 h1 = __float2bfloat16(v1);
    outh[o + lane]      = h0;
    outh[o + lane + 32] = h1;
    outl[o + lane]      = __float2bfloat16(v0 - __bfloat162float(h0));
    outl[o + lane + 32] = __float2bfloat16(v1 - __bfloat162float(h1));
}

// ---------------------------------------------------------------------------
extern "C" void kernel_launch(void* const* d_in, const int* in_sizes, int n_in,
                              void* d_out, int out_size) {
    const float* inL   = (const float*)d_in[0];
    const float* inN   = (const float*)d_in[1];
    const float* inO   = (const float*)d_in[2];
    const unsigned char* mask = (const unsigned char*)d_in[3];
    const float* aWq   = (const float*)d_in[4];
    const float* aWk   = (const float*)d_in[5];
    const float* aWv   = (const float*)d_in[6];
    const float* aGw   = (const float*)d_in[7];
    const float* aGb   = (const float*)d_in[8];
    const float* aOw   = (const float*)d_in[9];
    const float* aOb   = (const float*)d_in[10];
    const float* ln_g  = (const float*)d_in[11];
    const float* ln_b  = (const float*)d_in[12];
    const float* ff_g  = (const float*)d_in[13];
    const float* ff_b  = (const float*)d_in[14];
    const float* ff_w1 = (const float*)d_in[15];
    const float* ff_b1 = (const float*)d_in[16];
    const float* ff_w2 = (const float*)d_in[17];
    const float* ff_b2 = (const float*)d_in[18];

    float* out = (float*)d_out;
    float* L  = out;
    float* Nn = out + RD;
    float* O  = out + 2 * RD;

    float *Q, *K, *V, *G;
    bf16 *t1h, *t1l, *t2h, *t2l, *t3h, *t3l, *atth, *attl, *hidh, *hidl;
    bf16 *wqh, *wql, *wkh, *wkl, *wvh, *wvl, *wgh, *wgl, *woh, *wol;
    bf16 *w1h, *w1l, *w2h, *w2l;
    cudaGetSymbolAddress((void**)&Q, g_Q);     cudaGetSymbolAddress((void**)&K, g_K);
    cudaGetSymbolAddress((void**)&V, g_V);     cudaGetSymbolAddress((void**)&G, g_G);
    cudaGetSymbolAddress((void**)&t1h, g_t1h); cudaGetSymbolAddress((void**)&t1l, g_t1l);
    cudaGetSymbolAddress((void**)&t2h, g_t2h); cudaGetSymbolAddress((void**)&t2l, g_t2l);
    cudaGetSymbolAddress((void**)&t3h, g_t3h); cudaGetSymbolAddress((void**)&t3l, g_t3l);
    cudaGetSymbolAddress((void**)&atth, g_atth); cudaGetSymbolAddress((void**)&attl, g_attl);
    cudaGetSymbolAddress((void**)&hidh, g_hidh); cudaGetSymbolAddress((void**)&hidl, g_hidl);
    cudaGetSymbolAddress((void**)&wqh, g_wqh); cudaGetSymbolAddress((void**)&wql, g_wql);
    cudaGetSymbolAddress((void**)&wkh, g_wkh); cudaGetSymbolAddress((void**)&wkl, g_wkl);
    cudaGetSymbolAddress((void**)&wvh, g_wvh); cudaGetSymbolAddress((void**)&wvl, g_wvl);
    cudaGetSymbolAddress((void**)&wgh, g_wgh); cudaGetSymbolAddress((void**)&wgl, g_wgl);
    cudaGetSymbolAddress((void**)&woh, g_woh); cudaGetSymbolAddress((void**)&wol, g_wol);
    cudaGetSymbolAddress((void**)&w1h, g_w1h); cudaGetSymbolAddress((void**)&w1l, g_w1l);
    cudaGetSymbolAddress((void**)&w2h, g_w2h); cudaGetSymbolAddress((void**)&w2l, g_w2l);

    // ---- split + transpose weights (once per launch) ----
    {
        int tD = 7 * Dd * Dd;
        int bD = (tD + 255) / 256;
        split_w_kernel<<<bD, 256>>>(aWq, wqh, wql, Dd, Dd, tD);
        split_w_kernel<<<bD, 256>>>(aWk, wkh, wkl, Dd, Dd, tD);
        split_w_kernel<<<bD, 256>>>(aWv, wvh, wvl, Dd, Dd, tD);
        split_w_kernel<<<bD, 256>>>(aGw, wgh, wgl, Dd, Dd, tD);
        split_w_kernel<<<bD, 256>>>(aOw, woh, wol, Dd, Dd, tD);
        int tF = 6 * Dd * FFD;
        int bF = (tF + 255) / 256;
        split_w_kernel<<<bF, 256>>>(ff_w1, w1h, w1l, Dd, FFD, tF);   // -> [FFD][Dd]
        split_w_kernel<<<bF, 256>>>(ff_w2, w2h, w2l, FFD, Dd, tF);   // -> [Dd][FFD]
    }

    init_copy_kernel<<<RD / 256, 256>>>(inL, inN, inO, out);

    const dim3 gD(Dd / 32, RR / 64);        // (8, 32): N=256 out, NT=4
    const dim3 gQ(Dd / 32, RR / 64, 4);     // fused QKVG: 1024 blocks
    const dim3 gF(FFD / 64, RR / 64);       // (32, 32): N=2048 out, NT=8

    auto LN = [&](const float* x, const float* garr, const float* barr, int k,
                  bf16* oh, bf16* ol) {
        ln_kernel<<<RR, Dd>>>(x, garr + (size_t)k * Dd, barr + (size_t)k * Dd, oh, ol);
    };

    auto ATTN = [&](int k, const bf16* qh, const bf16* ql,
                    const bf16* kvh, const bf16* kvl, float* target) {
        size_t wo = (size_t)k * Dd * Dd;
        mma_qkvg_kernel<<<gQ, 128>>>(qh, ql, kvh, kvl,
                                     wqh + wo, wql + wo, wkh + wo, wkl + wo,
                                     wvh + wo, wvl + wo, wgh + wo, wgl + wo,
                                     aGb + (size_t)k * Dd, Q, K, V, G);
        attn_core_kernel<<<(Bb * Hh * Ss) / 4, 128>>>(Q, K, V, G, mask, atth, attl);
        mma_gemm_kernel<4, 2><<<gD, 128>>>(atth, attl, woh + wo, wol + wo,
                                           aOb + (size_t)k * Dd,
                                           target, nullptr, nullptr, Dd, Dd);
    };

    auto FF = [&](int k, float* x) {
        LN(x, ff_g, ff_b, k, t1h, t1l);
        mma_gemm_kernel<8, 3><<<gF, 128>>>(t1h, t1l,
                                           w1h + (size_t)k * Dd * FFD,
                                           w1l + (size_t)k * Dd * FFD,
                                           ff_b1 + (size_t)k * FFD,
                                           nullptr, hidh, hidl, FFD, Dd);
        mma_gemm_kernel<4, 2><<<gD, 128>>>(hidh, hidl,
                                           w2h + (size_t)k * FFD * Dd,
                                           w2l + (size_t)k * FFD * Dd,
                                           ff_b2 + (size_t)k * Dd,
                                           x, nullptr, nullptr, Dd, FFD);
    };

    for (int it = 0; it < 2; it++) {
        LN(L,  ln_g, ln_b, 0, t1h, t1l); ATTN(0, t1h, t1l, t1h, t1l, L);  FF(0, L);
        LN(Nn, ln_g, ln_b, 1, t1h, t1l); ATTN(1, t1h, t1l, t1h, t1l, Nn); FF(1, Nn);
        LN(O,  ln_g, ln_b, 2, t1h, t1l); ATTN(2, t1h, t1l, t1h, t1l, O);  FF(2, O);

        LN(O,  ln_g, ln_b, 3, t2h, t2l);                                   // tO (kv)
        LN(L,  ln_g, ln_b, 4, t1h, t1l); ATTN(3, t1h, t1l, t2h, t2l, L);  FF(3, L);
        LN(Nn, ln_g, ln_b, 5, t1h, t1l); ATTN(4, t1h, t1l, t2h, t2l, Nn); FF(4, Nn);

        LN(L,  ln_g, ln_b, 6, t1h, t1l);                                   // tL
        LN(Nn, ln_g, ln_b, 7, t3h, t3l);                                   // tN
        LN(O,  ln_g, ln_b, 8, t2h, t2l);                                   // tO
        ATTN(5, t2h, t2l, t3h, t3l, O);                                    // O += att5
        ATTN(6, t2h, t2l, t1h, t1l, O);                                    // O += att6
        FF(5, O);
    }
}

// round 13
// speedup vs baseline: 1.1425x; 1.1425x over previous
#include <cuda_runtime.h>
#include <cuda_bf16.h>
#include <cstdint>

// ---------------------------------------------------------------------------
// fusionEncodeBlock: B=2, S=1024, D=256, H=4, C=64, FF=2048, WIN=10, NITER=2
// bf16x2 split GEMMs (3-product, fp32 accumulate) on mma.sync tensor cores.
// Batched L/N/O streams; ldmatrix fragment loads; LN/softmax/epilogues fp32.
// ---------------------------------------------------------------------------

#define Bb   2
#define Ss   1024
#define Dd   256
#define Hh   4
#define Cc   64
#define FFD  2048
#define RR   (Bb * Ss)          // 2048 rows per stream
#define RD   (RR * Dd)          // 524288
#define DD   (Dd * Dd)          // 65536
#define WIN  10

typedef __nv_bfloat16 bf16;

// ---------------- scratch (allocation-free; 16B-aligned) -------------------
__device__ __align__(16) float g_Q[3 * RD];
__device__ __align__(16) float g_K[3 * RD];
__device__ __align__(16) float g_V[3 * RD];
__device__ __align__(16) float g_G[3 * RD];

__device__ __align__(16) bf16 g_t1h[3 * RD], g_t1l[3 * RD];
__device__ __align__(16) bf16 g_t2h[RD],     g_t2l[RD];
__device__ __align__(16) bf16 g_atth[3 * RD], g_attl[3 * RD];
__device__ __align__(16) bf16 g_hidh[3 * RR * FFD], g_hidl[3 * RR * FFD];

// split + transposed weights: stored [mat][N][K]
__device__ __align__(16) bf16 g_wqh[7 * DD],  g_wql[7 * DD];
__device__ __align__(16) bf16 g_wkh[7 * DD],  g_wkl[7 * DD];
__device__ __align__(16) bf16 g_wvh[7 * DD],  g_wvl[7 * DD];
__device__ __align__(16) bf16 g_wgh[7 * DD],  g_wgl[7 * DD];
__device__ __align__(16) bf16 g_woh[7 * DD],  g_wol[7 * DD];
__device__ __align__(16) bf16 g_w1h[6 * Dd * FFD], g_w1l[6 * Dd * FFD];
__device__ __align__(16) bf16 g_w2h[6 * FFD * Dd], g_w2l[6 * FFD * Dd];

// ---------------------------------------------------------------------------
__global__ void init_copy_kernel(const float* __restrict__ a,
                                 const float* __restrict__ b,
                                 const float* __restrict__ c,
                                 float* __restrict__ out) {
    int i = blockIdx.x * blockDim.x + threadIdx.x;
    out[i]          = a[i];
    out[i + RD]     = b[i];
    out[i + 2 * RD] = c[i];
}

// ---------------------------------------------------------------------------
// One fused split+transpose for all 7 weight tensors.
// src [mat][K][N] fp32 -> hi/lo [mat][N][K] bf16 (k fastest in dst).
#define CNT_D (7 * DD)            // 458752
#define CNT_F (6 * Dd * FFD)      // 3145728
#define SPLIT_TOTAL (5 * CNT_D + 2 * CNT_F)

__global__ void split_all_kernel(const float* __restrict__ aWq,
                                 const float* __restrict__ aWk,
                                 const float* __restrict__ aWv,
                                 const float* __restrict__ aGw,
                                 const float* __restrict__ aOw,
                                 const float* __restrict__ w1,
                                 const float* __restrict__ w2) {
    int i = blockIdx.x * blockDim.x + threadIdx.x;
    if (i >= SPLIT_TOTAL) return;

    const float* src;
    bf16 *dh, *dl;
    int K, N, local;
    if (i < 5 * CNT_D) {
        int sec = i / CNT_D;
        local = i - sec * CNT_D;
        K = Dd; N = Dd;
        switch (sec) {
            case 0: src = aWq; dh = g_wqh; dl = g_wql; break;
            case 1: src = aWk; dh = g_wkh; dl = g_wkl; break;
            case 2: src = aWv; dh = g_wvh; dl = g_wvl; break;
            case 3: src = aGw; dh = g_wgh; dl = g_wgl; break;
            default: src = aOw; dh = g_woh; dl = g_wol; break;
        }
    } else if (i < 5 * CNT_D + CNT_F) {
        local = i - 5 * CNT_D;
        src = w1; dh = g_w1h; dl = g_w1l; K = Dd; N = FFD;
    } else {
        local = i - 5 * CNT_D - CNT_F;
        src = w2; dh = g_w2h; dl = g_w2l; K = FFD; N = Dd;
    }
    int kn  = K * N;
    int mat = local / kn;
    int r   = local - mat * kn;
    int k   = r % K;
    int n   = r / K;
    float v = src[(size_t)mat * kn + (size_t)k * N + n];
    bf16 h = __float2bfloat16(v);
    dh[local] = h;
    dl[local] = __float2bfloat16(v - __bfloat162float(h));
}

// ---------------------------------------------------------------------------
// Batched LayerNorm: grid.x = nchunk*RR rows (contiguous in x); per-chunk
// gamma/beta index k = kbase + row/RR. Emits bf16 hi/lo split.
__global__ void __launch_bounds__(Dd) ln_kernel(const float* __restrict__ x,
                                                const float* __restrict__ garr,
                                                const float* __restrict__ barr,
                                                int kbase,
                                                bf16* __restrict__ oh,
                                                bf16* __restrict__ ol) {
    int row = blockIdx.x;
    int tid = threadIdx.x;
    int k   = kbase + row / RR;
    const float* g = garr + (size_t)k * Dd;
    const float* b = barr + (size_t)k * Dd;
    float v = x[(size_t)row * Dd + tid];

    float s = v;
    #pragma unroll
    for (int o = 16; o; o >>= 1) s += __shfl_xor_sync(0xffffffffu, s, o);

    __shared__ float ws[8];
    __shared__ float ws2[8];
    int w = tid >> 5, l = tid & 31;
    if (l == 0) ws[w] = s;
    __syncthreads();
    float mean = (ws[0] + ws[1] + ws[2] + ws[3] +
                  ws[4] + ws[5] + ws[6] + ws[7]) * (1.0f / Dd);

    float d = v - mean;
    float sq = d * d;
    #pragma unroll
    for (int o = 16; o; o >>= 1) sq += __shfl_xor_sync(0xffffffffu, sq, o);
    if (l == 0) ws2[w] = sq;
    __syncthreads();
    float var = (ws2[0] + ws2[1] + ws2[2] + ws2[3] +
                 ws2[4] + ws2[5] + ws2[6] + ws2[7]) * (1.0f / Dd);

    float y = d * rsqrtf(var + 1e-5f) * g[tid] + b[tid];
    bf16 h = __float2bfloat16(y);
    oh[(size_t)row * Dd + tid] = h;
    ol[(size_t)row * Dd + tid] = __float2bfloat16(y - __bfloat162float(h));
}

// ---------------------------------------------------------------------------
__device__ __forceinline__ void mma_bf16(float* c,
                                         uint32_t a0, uint32_t a1,
                                         uint32_t a2, uint32_t a3,
                                         uint32_t b0, uint32_t b1) {
    asm volatile(
        "mma.sync.aligned.m16n8k16.row.col.f32.bf16.bf16.f32 "
        "{%0,%1,%2,%3}, {%4,%5,%6,%7}, {%8,%9}, {%0,%1,%2,%3};"
        : "+f"(c[0]), "+f"(c[1]), "+f"(c[2]), "+f"(c[3])
        : "r"(a0), "r"(a1), "r"(a2), "r"(a3), "r"(b0), "r"(b1));
}

__device__ __forceinline__ void ldsm4(uint32_t& r0, uint32_t& r1,
                                      uint32_t& r2, uint32_t& r3,
                                      const bf16* p) {
    uint32_t a = (uint32_t)__cvta_generic_to_shared(p);
    asm volatile("ldmatrix.sync.aligned.m8n8.x4.shared.b16 {%0,%1,%2,%3}, [%4];"
                 : "=r"(r0), "=r"(r1), "=r"(r2), "=r"(r3) : "r"(a));
}

// ---------------------------------------------------------------------------
// Split-bf16 GEMM mainloop. C tile 64 x (NT*8), 128 threads (4 warps,
// warp w owns rows w*16..w*16+15). acc += Ah*Wh + Ah*Wl + Al*Wh.
// A hi/lo row-major [M][K]; W hi/lo transposed [N][K]. k-panel 16,
// reg-prefetch double-buffered smem, ldmatrix fragment loads.
template <int NT>
struct Smem {
    bf16 Ash[2][64][24], Asl[2][64][24];
    bf16 Wsh[2][NT * 8][24], Wsl[2][NT * 8][24];
};

template <int NT>
__device__ __forceinline__ void mma_mainloop(Smem<NT>& sm,
    const bf16* __restrict__ Ah, const bf16* __restrict__ Al,
    const bf16* __restrict__ Wh, const bf16* __restrict__ Wl,
    int bmA, int bn, int K, float (&acc)[NT][4]) {

    constexpr int BN   = NT * 8;
    constexpr int NSEG = (256 + 4 * BN) / 128;

    int tid = threadIdx.x;
    int warp = tid >> 5, lane = tid & 31;

    const bf16* sbase[NSEG];
    bf16*       dbase[NSEG];
    int         dstr[NSEG];
    #pragma unroll
    for (int i = 0; i < NSEG; i++) {
        int s = tid + i * 128;
        if (s < 256) {
            int hilo = s >> 7, r = (s >> 1) & 63, koff = (s & 1) * 8;
            sbase[i] = (hilo ? Al : Ah) + (size_t)(bmA + r) * K + koff;
            dbase[i] = (hilo ? &sm.Asl[0][0][0] : &sm.Ash[0][0][0]) + r * 24 + koff;
            dstr[i]  = 64 * 24;
        } else {
            int t = s - 256;
            int hilo = t / (2 * BN), n = (t >> 1) & (BN - 1), koff = (t & 1) * 8;
            sbase[i] = (hilo ? Wl : Wh) + (size_t)(bn + n) * K + koff;
            dbase[i] = (hilo ? &sm.Wsl[0][0][0] : &sm.Wsh[0][0][0]) + n * 24 + koff;
            dstr[i]  = BN * 24;
        }
    }

    __syncthreads();   // smem safe to overwrite (multi-call reuse)
    uint4 pref[NSEG];
    #pragma unroll
    for (int i = 0; i < NSEG; i++) pref[i] = *(const uint4*)(sbase[i]);
    #pragma unroll
    for (int i = 0; i < NSEG; i++) *(uint4*)(dbase[i]) = pref[i];
    __syncthreads();

    // ldmatrix lane addressing
    int a_row = warp * 16 + ((lane >> 3) & 1) * 8 + (lane & 7);
    int a_k   = (lane >> 4) * 8;
    int w_nrb = (lane >> 4) * 8 + (lane & 7);
    int w_k   = ((lane >> 3) & 1) * 8;

    int npanel = K >> 4;
    for (int p = 0; p < npanel; p++) {
        int buf = p & 1;
        bool more = (p + 1) < npanel;
        if (more) {
            int k0 = (p + 1) << 4;
            #pragma unroll
            for (int i = 0; i < NSEG; i++)
                pref[i] = *(const uint4*)(sbase[i] + k0);
        }

        uint32_t ah0, ah1, ah2, ah3, al0, al1, al2, al3;
        ldsm4(ah0, ah1, ah2, ah3, &sm.Ash[buf][a_row][a_k]);
        ldsm4(al0, al1, al2, al3, &sm.Asl[buf][a_row][a_k]);

        #pragma unroll
        for (int pr = 0; pr < NT / 2; pr++) {
            uint32_t bh0, bh1, bh2, bh3, bl0, bl1, bl2, bl3;
            ldsm4(bh0, bh1, bh2, bh3, &sm.Wsh[buf][pr * 16 + w_nrb][w_k]);
            ldsm4(bl0, bl1, bl2, bl3, &sm.Wsl[buf][pr * 16 + w_nrb][w_k]);
            mma_bf16(acc[2 * pr],     ah0, ah1, ah2, ah3, bh0, bh1);
            mma_bf16(acc[2 * pr],     ah0, ah1, ah2, ah3, bl0, bl1);
            mma_bf16(acc[2 * pr],     al0, al1, al2, al3, bh0, bh1);
            mma_bf16(acc[2 * pr + 1], ah0, ah1, ah2, ah3, bh2, bh3);
            mma_bf16(acc[2 * pr + 1], ah0, ah1, ah2, ah3, bl2, bl3);
            mma_bf16(acc[2 * pr + 1], al0, al1, al2, al3, bh2, bh3);
        }

        if (more) {
            int nb = buf ^ 1;
            #pragma unroll
            for (int i = 0; i < NSEG; i++)
                *(uint4*)(dbase[i] + nb * dstr[i]) = pref[i];
            __syncthreads();
        }
    }
}

// EPI: 0: C=AB  1: C=sigmoid(AB+bias)  2: C+=AB+bias
//      3: hi/lo=split(relu(AB+bias))   4: C+=AB+bias+bias2
template <int NT, int EPI>
__device__ __forceinline__ void gemm_epilogue(float (&acc)[NT][4],
                                              const float* __restrict__ bias,
                                              const float* __restrict__ bias2,
                                              float* __restrict__ C,
                                              bf16* __restrict__ Chi,
                                              bf16* __restrict__ Clo,
                                              int bmC, int bn, int N) {
    int tid = threadIdx.x;
    int warp = tid >> 5, lane = tid & 31;
    int row0 = bmC + warp * 16 + (lane >> 2);
    #pragma unroll
    for (int nt = 0; nt < NT; nt++) {
        int col = bn + nt * 8 + ((lane & 3) << 1);
        #pragma unroll
        for (int half = 0; half < 2; half++) {
            int row = row0 + half * 8;
            float v0 = acc[nt][half * 2 + 0];
            float v1 = acc[nt][half * 2 + 1];
            size_t o = (size_t)row * N + col;
            if (EPI == 0) {
                *(float2*)&C[o] = make_float2(v0, v1);
            } else if (EPI == 1) {
                v0 += bias[col];     v1 += bias[col + 1];
                v0 = 1.0f / (1.0f + __expf(-v0));
                v1 = 1.0f / (1.0f + __expf(-v1));
                *(float2*)&C[o] = make_float2(v0, v1);
            } else if (EPI == 2) {
                float2 old = *(float2*)&C[o];
                *(float2*)&C[o] = make_float2(old.x + v0 + bias[col],
                                              old.y + v1 + bias[col + 1]);
            } else if (EPI == 3) {
                v0 = fmaxf(v0 + bias[col],     0.0f);
                v1 = fmaxf(v1 + bias[col + 1], 0.0f);
                bf16 h0 = __float2bfloat16(v0);
                bf16 h1 = __float2bfloat16(v1);
                __nv_bfloat162 hv; hv.x = h0; hv.y = h1;
                __nv_bfloat162 lv;
                lv.x = __float2bfloat16(v0 - __bfloat162float(h0));
                lv.y = __float2bfloat16(v1 - __bfloat162float(h1));
                *(__nv_bfloat162*)&Chi[o] = hv;
                *(__nv_bfloat162*)&Clo[o] = lv;
            } else {  // EPI == 4
                float2 old = *(float2*)&C[o];
                *(float2*)&C[o] = make_float2(
                    old.x + v0 + bias[col]     + bias2[col],
                    old.y + v1 + bias[col + 1] + bias2[col + 1]);
            }
        }
    }
}

// ---------------------------------------------------------------------------
// Generic batched GEMM vs a weight bank: chunk = blockIdx.y/32 selects
// m = mbase+chunk; A and C rows are global (bm = blockIdx.y*64).
template <int NT, int EPI>
__global__ void __launch_bounds__(128) gemm_w_kernel(
    const bf16* __restrict__ Ah, const bf16* __restrict__ Al,
    const bf16* __restrict__ Whb, const bf16* __restrict__ Wlb,
    size_t wstride, const float* __restrict__ biasb, int bstride, int mbase,
    float* __restrict__ C, bf16* __restrict__ Chi, bf16* __restrict__ Clo,
    int N, int K) {

    __shared__ Smem<NT> sm;
    int chunk = blockIdx.y >> 5;
    int m = mbase + chunk;
    const bf16* Wh = Whb + (size_t)m * wstride;
    const bf16* Wl = Wlb + (size_t)m * wstride;
    int bm = blockIdx.y * 64, bn = blockIdx.x * (NT * 8);

    float acc[NT][4] = {};
    mma_mainloop<NT>(sm, Ah, Al, Wh, Wl, bm, bn, K, acc);
    gemm_epilogue<NT, EPI>(acc, biasb + (size_t)m * bstride, nullptr,
                           C, Chi, Clo, bm, bn, N);
}

// Batched fused Q/K/V/G projection. blockIdx.z: 0=Q 1=K 2=V 3=G.
// chunk = blockIdx.y/32; per-chunk A element-offsets for q and kv.
__global__ void __launch_bounds__(128) qkvg_kernel(
    const bf16* __restrict__ qh, const bf16* __restrict__ ql,
    const bf16* __restrict__ kvh, const bf16* __restrict__ kvl,
    int qo0, int qo1, int qo2, int ko0, int ko1, int ko2,
    int mbase,
    const bf16* __restrict__ wqh, const bf16* __restrict__ wql,
    const bf16* __restrict__ wkh, const bf16* __restrict__ wkl,
    const bf16* __restrict__ wvh, const bf16* __restrict__ wvl,
    const bf16* __restrict__ wgh, const bf16* __restrict__ wgl,
    const float* __restrict__ aGb,
    float* __restrict__ Qo, float* __restrict__ Ko,
    float* __restrict__ Vo, float* __restrict__ Go) {

    __shared__ Smem<4> sm;
    int chunk = blockIdx.y >> 5;
    int qoff = (chunk == 0) ? qo0 : (chunk == 1) ? qo1 : qo2;
    int koff = (chunk == 0) ? ko0 : (chunk == 1) ? ko1 : ko2;
    int m = mbase + chunk;
    int z = blockIdx.z;

    const bf16 *Ah, *Al, *Wh, *Wl;
    float* C;
    if (z == 0)      { Ah = qh + qoff;  Al = ql + qoff;
                       Wh = wqh + (size_t)m * DD; Wl = wql + (size_t)m * DD; C = Qo; }
    else if (z == 1) { Ah = kvh + koff; Al = kvl + koff;
                       Wh = wkh + (size_t)m * DD; Wl = wkl + (size_t)m * DD; C = Ko; }
    else if (z == 2) { Ah = kvh + koff; Al = kvl + koff;
                       Wh = wvh + (size_t)m * DD; Wl = wvl + (size_t)m * DD; C = Vo; }
    else             { Ah = kvh + koff; Al = kvl + koff;
                       Wh = wgh + (size_t)m * DD; Wl = wgl + (size_t)m * DD; C = Go; }

    int bmA = (blockIdx.y & 31) * 64;     // row within chunk's A buffer
    int bmC = blockIdx.y * 64;            // global output row
    int bn  = blockIdx.x * 32;

    float acc[4][4] = {};
    mma_mainloop<4>(sm, Ah, Al, Wh, Wl, bmA, bn, Dd, acc);
    if (z == 3) gemm_epilogue<4, 1>(acc, aGb + (size_t)m * Dd, nullptr,
                                    C, nullptr, nullptr, bmC, bn, Dd);
    else        gemm_epilogue<4, 0>(acc, nullptr, nullptr,
                                    C, nullptr, nullptr, bmC, bn, Dd);
}

// Phase-3 dual projection: O += att5 @ Wo5 + att6 @ Wo6 (+ both biases).
__global__ void __launch_bounds__(128) proj_dual_kernel(
    const bf16* __restrict__ atth, const bf16* __restrict__ attl,
    const bf16* __restrict__ wo5h, const bf16* __restrict__ wo5l,
    const bf16* __restrict__ wo6h, const bf16* __restrict__ wo6l,
    const float* __restrict__ b5, const float* __restrict__ b6,
    float* __restrict__ C) {

    __shared__ Smem<4> sm;
    int bm = blockIdx.y * 64, bn = blockIdx.x * 32;
    float acc[4][4] = {};
    mma_mainloop<4>(sm, atth,      attl,      wo5h, wo5l, bm, bn, Dd, acc);
    mma_mainloop<4>(sm, atth + RD, attl + RD, wo6h, wo6l, bm, bn, Dd, acc);
    gemm_epilogue<4, 4>(acc, b5, b6, C, nullptr, nullptr, bm, bn, Dd);
}

// ---------------------------------------------------------------------------
// Batched local-window gated attention core (fp32). One warp per (chunk,n,h,s).
__global__ void __launch_bounds__(128) attn_core_kernel(
    const float* __restrict__ Q, const float* __restrict__ Kp,
    const float* __restrict__ V, const float* __restrict__ G,
    const unsigned char* __restrict__ mask,
    bf16* __restrict__ outh, bf16* __restrict__ outl) {

    int wid  = blockIdx.x * 4 + (threadIdx.x >> 5);
    int lane = threadIdx.x & 31;
    int s = wid & (Ss - 1);
    int h = (wid >> 10) & (Hh - 1);
    int n = (wid >> 12) & (Bb - 1);
    int chunk = wid >> 13;

    size_t rbase = (size_t)chunk * RR + n * Ss;
    const float* Qr = Q + (rbase + s) * Dd + h * Cc;
    float q0 = Qr[lane], q1 = Qr[lane + 32];

    float sc[2 * WIN + 1];
    float m = -1e30f;
    #pragma unroll
    for (int i = 0; i < 2 * WIN + 1; i++) {
        int t  = s - WIN + i;
        int tc = min(max(t, 0), Ss - 1);
        const float* Kr = Kp + (rbase + tc) * Dd + h * Cc;
        float p = q0 * Kr[lane] + q1 * Kr[lane + 32];
        #pragma unroll
        for (int o = 16; o; o >>= 1) p += __shfl_xor_sync(0xffffffffu, p, o);
        p *= 0.125f;                                   // 1/sqrt(64)
        if (t != tc || mask[n * Ss + tc]) p = -1e30f;  // window edge / seq mask
        sc[i] = p;
        m = fmaxf(m, p);
    }

    float den = 0.0f;
    #pragma unroll
    for (int i = 0; i < 2 * WIN + 1; i++) {
        sc[i] = __expf(sc[i] - m);
        den += sc[i];
    }
    float inv = 1.0f / den;

    float a0 = 0.0f, a1 = 0.0f;
    #pragma unroll
    for (int i = 0; i < 2 * WIN + 1; i++) {
        int t  = s - WIN + i;
        int tc = min(max(t, 0), Ss - 1);
        const float* Vr = V + (rbase + tc) * Dd + h * Cc;
        float w = sc[i] * inv;
        a0 += w * Vr[lane];
        a1 += w * Vr[lane + 32];
    }

    size_t o = (rbase + s) * Dd + h * Cc;
    float v0 = a0 * G[o + lane];
    float v1 = a1 * G[o + lane + 32];
    bf16 h0 = __float2bfloat16(v0);
    bf16 h1 = __float2bfloat16(v1);
    outh[o + lane]      = h0;
    outh[o + lane + 32] = h1;
    outl[o + lane]      = __float2bfloat16(v0 - __bfloat162float(h0));
    outl[o + lane + 32] = __float2bfloat16(v1 - __bfloat162float(h1));
}

// ---------------------------------------------------------------------------
extern "C" void kernel_launch(void* const* d_in, const int* in_sizes, int n_in,
                              void* d_out, int out_size) {
    const float* inL   = (const float*)d_in[0];
    const float* inN   = (const float*)d_in[1];
    const float* inO   = (const float*)d_in[2];
    const unsigned char* mask = (const unsigned char*)d_in[3];
    const float* aWq   = (const float*)d_in[4];
    const float* aWk   = (const float*)d_in[5];
    const float* aWv   = (const float*)d_in[6];
    const float* aGw   = (const float*)d_in[7];
    const float* aGb   = (const float*)d_in[8];
    const float* aOw   = (const float*)d_in[9];
    const float* aOb   = (const float*)d_in[10];
    const float* ln_g  = (const float*)d_in[11];
    const float* ln_b  = (const float*)d_in[12];
    const float* ff_g  = (const float*)d_in[13];
    const float* ff_b  = (const float*)d_in[14];
    const float* ff_w1 = (const float*)d_in[15];
    const float* ff_b1 = (const float*)d_in[16];
    const float* ff_w2 = (const float*)d_in[17];
    const float* ff_b2 = (const float*)d_in[18];

    float* out = (float*)d_out;

    float *Q, *Kf, *V, *G;
    bf16 *t1h, *t1l, *t2h, *t2l, *atth, *attl, *hidh, *hidl;
    bf16 *wqh, *wql, *wkh, *wkl, *wvh, *wvl, *wgh, *wgl, *woh, *wol;
    bf16 *w1h, *w1l, *w2h, *w2l;
    cudaGetSymbolAddress((void**)&Q, g_Q);     cudaGetSymbolAddress((void**)&Kf, g_K);
    cudaGetSymbolAddress((void**)&V, g_V);     cudaGetSymbolAddress((void**)&G, g_G);
    cudaGetSymbolAddress((void**)&t1h, g_t1h); cudaGetSymbolAddress((void**)&t1l, g_t1l);
    cudaGetSymbolAddress((void**)&t2h, g_t2h); cudaGetSymbolAddress((void**)&t2l, g_t2l);
    cudaGetSymbolAddress((void**)&atth, g_atth); cudaGetSymbolAddress((void**)&attl, g_attl);
    cudaGetSymbolAddress((void**)&hidh, g_hidh); cudaGetSymbolAddress((void**)&hidl, g_hidl);
    cudaGetSymbolAddress((void**)&wqh, g_wqh); cudaGetSymbolAddress((void**)&wql, g_wql);
    cudaGetSymbolAddress((void**)&wkh, g_wkh); cudaGetSymbolAddress((void**)&wkl, g_wkl);
    cudaGetSymbolAddress((void**)&wvh, g_wvh); cudaGetSymbolAddress((void**)&wvl, g_wvl);
    cudaGetSymbolAddress((void**)&wgh, g_wgh); cudaGetSymbolAddress((void**)&wgl, g_wgl);
    cudaGetSymbolAddress((void**)&woh, g_woh); cudaGetSymbolAddress((void**)&wol, g_wol);
    cudaGetSymbolAddress((void**)&w1h, g_w1h); cudaGetSymbolAddress((void**)&w1l, g_w1l);
    cudaGetSymbolAddress((void**)&w2h, g_w2h); cudaGetSymbolAddress((void**)&w2l, g_w2l);

    split_all_kernel<<<(SPLIT_TOTAL + 255) / 256, 256>>>(
        aWq, aWk, aWv, aGw, aOw, ff_w1, ff_w2);
    init_copy_kernel<<<RD / 256, 256>>>(inL, inN, inO, out);

    auto QKVG = [&](int nchunk, int mbase,
                    const bf16* qhb, const bf16* qlb,
                    const bf16* kvhb, const bf16* kvlb,
                    int qo0, int qo1, int qo2, int ko0, int ko1, int ko2) {
        dim3 g(8, nchunk * 32, 4);
        qkvg_kernel<<<g, 128>>>(qhb, qlb, kvhb, kvlb,
                                qo0, qo1, qo2, ko0, ko1, ko2, mbase,
                                wqh, wql, wkh, wkl, wvh, wvl, wgh, wgl,
                                aGb, Q, Kf, V, G);
    };
    auto CORE = [&](int nchunk) {
        attn_core_kernel<<<nchunk * 2048, 128>>>(Q, Kf, V, G, mask, atth, attl);
    };
    auto PROJ = [&](int nchunk, int mbase, float* C) {
        gemm_w_kernel<4, 2><<<dim3(8, nchunk * 32), 128>>>(
            atth, attl, woh, wol, DD, aOb, Dd, mbase, C, nullptr, nullptr, Dd, Dd);
    };
    auto FF = [&](int nchunk, int kbase, float* x) {
        ln_kernel<<<nchunk * RR, Dd>>>(x, ff_g, ff_b, kbase, t1h, t1l);
        gemm_w_kernel<8, 3><<<dim3(32, nchunk * 32), 128>>>(
            t1h, t1l, w1h, w1l, (size_t)Dd * FFD, ff_b1, FFD, kbase,
            nullptr, hidh, hidl, FFD, Dd);
        gemm_w_kernel<4, 2><<<dim3(8, nchunk * 32), 128>>>(
            hidh, hidl, w2h, w2l, (size_t)FFD * Dd, ff_b2, Dd, kbase,
            x, nullptr, nullptr, Dd, FFD);
    };

    for (int it = 0; it < 2; it++) {
        // Phase 1: three independent self-attention blocks (L, N, O)
        ln_kernel<<<3 * RR, Dd>>>(out, ln_g, ln_b, 0, t1h, t1l);
        QKVG(3, 0, t1h, t1l, t1h, t1l, 0, RD, 2 * RD, 0, RD, 2 * RD);
        CORE(3);
        PROJ(3, 0, out);
        FF(3, 0, out);

        // Phase 2: L and N cross-attend to tO
        ln_kernel<<<RR, Dd>>>(out + 2 * RD, ln_g, ln_b, 3, t2h, t2l);   // tO
        ln_kernel<<<2 * RR, Dd>>>(out, ln_g, ln_b, 4, t1h, t1l);        // tL, tN
        QKVG(2, 3, t1h, t1l, t2h, t2l, 0, RD, 0, 0, 0, 0);
        CORE(2);
        PROJ(2, 3, out);
        FF(2, 3, out);

        // Phase 3: O attends to tN (m=5) and tL (m=6)
        ln_kernel<<<3 * RR, Dd>>>(out, ln_g, ln_b, 6, t1h, t1l);        // tL,tN,tO
        QKVG(2, 5, t1h, t1l, t1h, t1l, 2 * RD, 2 * RD, 0, RD, 0, 0);
        CORE(2);
        proj_dual_kernel<<<dim3(8, 32), 128>>>(
            atth, attl, woh + 5 * DD, wol + 5 * DD, woh + 6 * DD, wol + 6 * DD,
            aOb + 5 * Dd, aOb + 6 * Dd, out + 2 * RD);
        FF(1, 5, out + 2 * RD);
    }
}